// round 1
// baseline (speedup 1.0000x reference)
#include <cuda_runtime.h>
#include <cuda_bf16.h>

#define VOCAB 50257
#define BATCH 512
#define SEQ   512

// Interleaved weight table: g_Wp[v] = {W[0][v], W[1][v]} so each token needs
// ONE 8-byte gather instead of two 4-byte gathers 200KB apart.
__device__ float2 g_Wp[VOCAB];

__global__ void interleave_W_kernel(const float* __restrict__ W) {
    int v = blockIdx.x * blockDim.x + threadIdx.x;
    if (v < VOCAB) {
        g_Wp[v] = make_float2(__ldg(W + v), __ldg(W + VOCAB + v));
    }
}

__global__ __launch_bounds__(SEQ) void bow_logits_kernel(
    const int*   __restrict__ ids,
    const float* __restrict__ bias,
    float*       __restrict__ out)
{
    const int row = blockIdx.x;
    const int tid = threadIdx.x;

    // One token per thread (blockDim == SEQ == 512).
    int id = __ldg(ids + row * SEQ + tid);
    float s0 = 0.f, s1 = 0.f;
    if (id != 0) {
        float2 w = g_Wp[id];
        s0 = w.x;
        s1 = w.y;
    }

    // Warp reduction.
    #pragma unroll
    for (int o = 16; o > 0; o >>= 1) {
        s0 += __shfl_down_sync(0xffffffffu, s0, o);
        s1 += __shfl_down_sync(0xffffffffu, s1, o);
    }

    __shared__ float2 sm[16];
    int w = tid >> 5, l = tid & 31;
    if (l == 0) sm[w] = make_float2(s0, s1);
    __syncthreads();

    if (w == 0) {
        float2 v = (l < 16) ? sm[l] : make_float2(0.f, 0.f);
        s0 = v.x; s1 = v.y;
        #pragma unroll
        for (int o = 8; o > 0; o >>= 1) {
            s0 += __shfl_down_sync(0xffffffffu, s0, o);
            s1 += __shfl_down_sync(0xffffffffu, s1, o);
        }
        if (l == 0) {
            out[row * 2 + 0] = s0 + __ldg(bias + 0);
            out[row * 2 + 1] = s1 + __ldg(bias + 1);
        }
    }
}

extern "C" void kernel_launch(void* const* d_in, const int* in_sizes, int n_in,
                              void* d_out, int out_size) {
    const int*   ids  = (const int*)  d_in[0];  // input_ids [512, 512] int32
    const float* W    = (const float*)d_in[1];  // W [2, 50257] fp32
    const float* bias = (const float*)d_in[2];  // b [2] fp32
    float*       out  = (float*)d_out;          // logits [512, 2] fp32

    interleave_W_kernel<<<(VOCAB + 255) / 256, 256>>>(W);
    bow_logits_kernel<<<BATCH, SEQ>>>(ids, bias, out);
}

// round 2
// speedup vs baseline: 1.1467x; 1.1467x over previous
#include <cuda_runtime.h>
#include <cuda_bf16.h>

#define VOCAB 50257
#define BATCH 512
#define SEQ   512
#define TPB   128          // threads per block; 4 tokens per thread

__global__ __launch_bounds__(TPB) void bow_logits_kernel(
    const int*   __restrict__ ids,
    const float* __restrict__ W,     // [2, VOCAB]
    const float* __restrict__ bias,  // [2]
    float*       __restrict__ out)   // [BATCH, 2]
{
    const int row = blockIdx.x;
    const int tid = threadIdx.x;

    // 4 tokens per thread via one coalesced 16B load.
    const int4 t4 = *reinterpret_cast<const int4*>(ids + row * SEQ + tid * 4);

    const float* __restrict__ W0 = W;
    const float* __restrict__ W1 = W + VOCAB;

    // 8 independent gathers — front-batched by ptxas for high MLP.
    // id==0 is the pad token: redirect to slot 0 but zero the contribution.
    float a0 = (t4.x != 0) ? __ldg(W0 + t4.x) : 0.f;
    float a1 = (t4.y != 0) ? __ldg(W0 + t4.y) : 0.f;
    float a2 = (t4.z != 0) ? __ldg(W0 + t4.z) : 0.f;
    float a3 = (t4.w != 0) ? __ldg(W0 + t4.w) : 0.f;
    float b0 = (t4.x != 0) ? __ldg(W1 + t4.x) : 0.f;
    float b1 = (t4.y != 0) ? __ldg(W1 + t4.y) : 0.f;
    float b2 = (t4.z != 0) ? __ldg(W1 + t4.z) : 0.f;
    float b3 = (t4.w != 0) ? __ldg(W1 + t4.w) : 0.f;

    float s0 = (a0 + a1) + (a2 + a3);
    float s1 = (b0 + b1) + (b2 + b3);

    // Warp reduction.
    #pragma unroll
    for (int o = 16; o > 0; o >>= 1) {
        s0 += __shfl_down_sync(0xffffffffu, s0, o);
        s1 += __shfl_down_sync(0xffffffffu, s1, o);
    }

    __shared__ float2 sm[TPB / 32];
    const int w = tid >> 5, l = tid & 31;
    if (l == 0) sm[w] = make_float2(s0, s1);
    __syncthreads();

    if (tid == 0) {
        float r0 = 0.f, r1 = 0.f;
        #pragma unroll
        for (int i = 0; i < TPB / 32; i++) { r0 += sm[i].x; r1 += sm[i].y; }
        out[row * 2 + 0] = r0 + __ldg(bias + 0);
        out[row * 2 + 1] = r1 + __ldg(bias + 1);
    }
}

extern "C" void kernel_launch(void* const* d_in, const int* in_sizes, int n_in,
                              void* d_out, int out_size) {
    const int*   ids  = (const int*)  d_in[0];  // input_ids [512, 512] int32
    const float* W    = (const float*)d_in[1];  // W [2, 50257] fp32
    const float* bias = (const float*)d_in[2];  // b [2] fp32
    float*       out  = (float*)d_out;          // logits [512, 2] fp32

    bow_logits_kernel<<<BATCH, TPB>>>(ids, W, bias, out);
}